// round 8
// baseline (speedup 1.0000x reference)
#include <cuda_runtime.h>

// out[i, :] = values[i] * W_D[layer_idx[i], feat_idx[i], :]
// W_D: (12, 16384, 768) fp32; nnz = 131072; d_model = 768 (3072 B/row).
//
// cp.async staging: 8 rows/CTA, 192 threads. Each thread issues 8
// cp.async.cg (16B, L2-only) gathers into smem -- async depth costs ZERO
// registers, so we get high occupancy (smem-limited ~9 CTAs/SM) AND
// depth-8 in-flight loads simultaneously (~200KB in flight per SM).
// Each thread consumes only its own staged bytes: no __syncthreads needed,
// cp.async.wait_group 0 suffices. Stores: __stwt (write-through).

#define D_SAE   16384
#define D_MODEL 768
#define VEC_PER_ROW (D_MODEL / 4)   // 192
#define ROWS_PER_CTA 8

__global__ __launch_bounds__(VEC_PER_ROW)
void gather_scale_kernel(const float4* __restrict__ W,
                         const float*  __restrict__ vals,
                         const int*    __restrict__ li,
                         const int*    __restrict__ fi,
                         float4*       __restrict__ out)
{
    __shared__ float4 buf[ROWS_PER_CTA * VEC_PER_ROW];   // 24576 B

    const int row0 = blockIdx.x * ROWS_PER_CTA;
    const int c    = threadIdx.x;

    float v[ROWS_PER_CTA];

    // smem base (u32) for this thread's 8 slots
    unsigned int sbase = (unsigned int)__cvta_generic_to_shared(&buf[c]);

#pragma unroll
    for (int r = 0; r < ROWS_PER_CTA; r++) {
        const int row   = row0 + r;
        const int layer = __ldg(&li[row]);
        const int feat  = __ldg(&fi[row]);
        v[r]            = __ldg(&vals[row]);
        const float4* src = &W[(unsigned int)(layer * D_SAE + feat) * VEC_PER_ROW + c];
        // 16B async copy, .cg = L2-only (skip L1)
        asm volatile("cp.async.cg.shared.global [%0], [%1], 16;\n"
                     :: "r"(sbase + r * (VEC_PER_ROW * 16)), "l"(src));
    }
    asm volatile("cp.async.commit_group;\n");
    asm volatile("cp.async.wait_group 0;\n" ::: "memory");

    // each thread reads back only the bytes it copied -> no barrier needed
#pragma unroll
    for (int r = 0; r < ROWS_PER_CTA; r++) {
        float4 o = buf[r * VEC_PER_ROW + c];
        o.x *= v[r]; o.y *= v[r]; o.z *= v[r]; o.w *= v[r];
        __stwt(&out[(unsigned int)(row0 + r) * VEC_PER_ROW + c], o);
    }
}

extern "C" void kernel_launch(void* const* d_in, const int* in_sizes, int n_in,
                              void* d_out, int out_size)
{
    const float4* W    = (const float4*)d_in[0];
    const float*  vals = (const float*) d_in[1];
    const int*    li   = (const int*)   d_in[2];
    // d_in[3] = pos_idx (unused)
    const int*    fi   = (const int*)   d_in[4];
    float4*       out  = (float4*)      d_out;

    const int nnz  = in_sizes[1];                // 131072 (divisible by 8)
    const int grid = nnz / ROWS_PER_CTA;         // 16384

    gather_scale_kernel<<<grid, VEC_PER_ROW>>>(W, vals, li, fi, out);
}

// round 11
// speedup vs baseline: 1.0018x; 1.0018x over previous
#include <cuda_runtime.h>

// out[i, :] = values[i] * W_D[layer_idx[i], feat_idx[i], :]
// W_D: (12, 16384, 768) fp32; nnz = 131072; d_model = 768 (3072 B/row).
//
// R7: bulk-store write path. Gather via cp.async.cg (depth-8, reg-free),
// scale, write scaled row into smem, then ONE cp.async.bulk (UBLKCP) 3072B
// store per row: presents each output row as a single contiguous bulk
// write transaction (24 sectors batched) instead of 192 scattered STG.128
// wavefronts -> lower LTS request pressure, better DRAM write bursts.

#define D_SAE   16384
#define D_MODEL 768
#define VEC_PER_ROW (D_MODEL / 4)   // 192
#define ROWS_PER_CTA 8
#define ROW_BYTES (D_MODEL * 4)     // 3072

__global__ __launch_bounds__(VEC_PER_ROW)
void gather_scale_kernel(const float4* __restrict__ W,
                         const float*  __restrict__ vals,
                         const int*    __restrict__ li,
                         const int*    __restrict__ fi,
                         float4*       __restrict__ out)
{
    __shared__ __align__(16) float4 buf[ROWS_PER_CTA * VEC_PER_ROW];  // 24576 B

    const int row0 = blockIdx.x * ROWS_PER_CTA;
    const int c    = threadIdx.x;

    float v[ROWS_PER_CTA];

    unsigned int sbase = (unsigned int)__cvta_generic_to_shared(&buf[c]);

#pragma unroll
    for (int r = 0; r < ROWS_PER_CTA; r++) {
        const int row   = row0 + r;
        const int layer = __ldg(&li[row]);
        const int feat  = __ldg(&fi[row]);
        v[r]            = __ldg(&vals[row]);
        const float4* src = &W[(unsigned int)(layer * D_SAE + feat) * VEC_PER_ROW + c];
        asm volatile("cp.async.cg.shared.global [%0], [%1], 16;\n"
                     :: "r"(sbase + r * (VEC_PER_ROW * 16)), "l"(src));
    }
    asm volatile("cp.async.commit_group;\n");
    asm volatile("cp.async.wait_group 0;\n" ::: "memory");

    // scale in place (each thread touches only its own staged slots)
#pragma unroll
    for (int r = 0; r < ROWS_PER_CTA; r++) {
        float4 o = buf[r * VEC_PER_ROW + c];
        o.x *= v[r]; o.y *= v[r]; o.z *= v[r]; o.w *= v[r];
        buf[r * VEC_PER_ROW + c] = o;
    }

    // make generic smem writes visible to the async (bulk-copy) proxy
    asm volatile("fence.proxy.async.shared::cta;\n" ::: "memory");
    __syncthreads();

    // threads 0..7: one 3072B bulk store per row (contiguous burst)
    if (c < ROWS_PER_CTA) {
        const int r = c;
        unsigned int srow = (unsigned int)__cvta_generic_to_shared(&buf[r * VEC_PER_ROW]);
        float4* dst = &out[(unsigned int)(row0 + r) * VEC_PER_ROW];
        asm volatile("cp.async.bulk.global.shared::cta.bulk_group [%0], [%1], %2;\n"
                     :: "l"(dst), "r"(srow), "r"(ROW_BYTES));
        asm volatile("cp.async.bulk.commit_group;\n");
        asm volatile("cp.async.bulk.wait_group 0;\n" ::: "memory");
    }
}

extern "C" void kernel_launch(void* const* d_in, const int* in_sizes, int n_in,
                              void* d_out, int out_size)
{
    const float4* W    = (const float4*)d_in[0];
    const float*  vals = (const float*) d_in[1];
    const int*    li   = (const int*)   d_in[2];
    // d_in[3] = pos_idx (unused)
    const int*    fi   = (const int*)   d_in[4];
    float4*       out  = (float4*)      d_out;

    const int nnz  = in_sizes[1];                // 131072 (divisible by 8)
    const int grid = nnz / ROWS_PER_CTA;         // 16384

    gather_scale_kernel<<<grid, VEC_PER_ROW>>>(W, vals, li, fi, out);
}

// round 14
// speedup vs baseline: 1.0036x; 1.0018x over previous
#include <cuda_runtime.h>

// out[i, :] = values[i] * W_D[layer_idx[i], feat_idx[i], :]
// W_D: (12, 16384, 768) fp32; nnz = 131072; d_model = 768 (3072 B/row).
//
// R8: bulk transactions on BOTH sides. Per gathered row:
//   one cp.async.bulk 3072B read (global->smem, mbarrier complete_tx)
//   scale in regs (LDS/FFMA/STS)
//   one cp.async.bulk 3072B write (smem->global, bulk_group)
// Each row is a single contiguous burst at the memory controller in both
// directions -> fewer DRAM row activates / read-write turnarounds, which is
// the hypothesized cause of the 79% DRAM-busy ceiling.

#define D_SAE   16384
#define D_MODEL 768
#define VEC_PER_ROW (D_MODEL / 4)   // 192
#define ROWS_PER_CTA 8
#define ROW_BYTES (D_MODEL * 4)     // 3072
#define TILE_BYTES (ROWS_PER_CTA * ROW_BYTES)  // 24576

__global__ __launch_bounds__(VEC_PER_ROW)
void gather_scale_kernel(const float4* __restrict__ W,
                         const float*  __restrict__ vals,
                         const int*    __restrict__ li,
                         const int*    __restrict__ fi,
                         float4*       __restrict__ out)
{
    __shared__ __align__(16) float4 buf[ROWS_PER_CTA * VEC_PER_ROW];  // 24576 B
    __shared__ __align__(8)  unsigned long long mbar;

    const int row0 = blockIdx.x * ROWS_PER_CTA;
    const int c    = threadIdx.x;

    const unsigned int mbar_u32 =
        (unsigned int)__cvta_generic_to_shared(&mbar);

    if (c == 0) {
        asm volatile("mbarrier.init.shared.b64 [%0], 1;\n"
                     :: "r"(mbar_u32) : "memory");
    }
    __syncthreads();

    // one 3072B bulk read per row, all completing on the same mbarrier
    if (c == 0) {
        asm volatile("mbarrier.arrive.expect_tx.shared.b64 _, [%0], %1;\n"
                     :: "r"(mbar_u32), "r"((unsigned)TILE_BYTES) : "memory");
    }
    if (c < ROWS_PER_CTA) {
        const int   r     = c;
        const int   row   = row0 + r;
        const int   layer = __ldg(&li[row]);
        const int   feat  = __ldg(&fi[row]);
        const float4* src = &W[(unsigned int)(layer * D_SAE + feat) * VEC_PER_ROW];
        const unsigned int sdst =
            (unsigned int)__cvta_generic_to_shared(&buf[r * VEC_PER_ROW]);
        asm volatile(
            "cp.async.bulk.shared::cta.global.mbarrier::complete_tx::bytes "
            "[%0], [%1], %2, [%3];\n"
            :: "r"(sdst), "l"(src), "r"((unsigned)ROW_BYTES), "r"(mbar_u32)
            : "memory");
    }

    // per-row scales (cheap scalar loads, overlap with bulk reads)
    float v[ROWS_PER_CTA];
#pragma unroll
    for (int r = 0; r < ROWS_PER_CTA; r++)
        v[r] = __ldg(&vals[row0 + r]);

    // wait for all 8 bulk reads (acquire orders the LDS below)
    {
        asm volatile(
            "{\n\t"
            ".reg .pred P;\n\t"
            "WAIT_%=:\n\t"
            "mbarrier.try_wait.parity.acquire.cta.shared::cta.b64 P, [%0], 0, 0x989680;\n\t"
            "@!P bra WAIT_%=;\n\t"
            "}\n"
            :: "r"(mbar_u32) : "memory");
    }

    // scale in place
#pragma unroll
    for (int r = 0; r < ROWS_PER_CTA; r++) {
        float4 o = buf[r * VEC_PER_ROW + c];
        o.x *= v[r]; o.y *= v[r]; o.z *= v[r]; o.w *= v[r];
        buf[r * VEC_PER_ROW + c] = o;
    }

    // make generic smem writes visible to the async proxy
    asm volatile("fence.proxy.async.shared::cta;\n" ::: "memory");
    __syncthreads();

    // one 3072B bulk write per row
    if (c < ROWS_PER_CTA) {
        const int r = c;
        const unsigned int srow =
            (unsigned int)__cvta_generic_to_shared(&buf[r * VEC_PER_ROW]);
        float4* dst = &out[(unsigned int)(row0 + r) * VEC_PER_ROW];
        asm volatile("cp.async.bulk.global.shared::cta.bulk_group [%0], [%1], %2;\n"
                     :: "l"(dst), "r"(srow), "r"((unsigned)ROW_BYTES) : "memory");
        asm volatile("cp.async.bulk.commit_group;\n");
        asm volatile("cp.async.bulk.wait_group 0;\n" ::: "memory");
    }
}

extern "C" void kernel_launch(void* const* d_in, const int* in_sizes, int n_in,
                              void* d_out, int out_size)
{
    const float4* W    = (const float4*)d_in[0];
    const float*  vals = (const float*) d_in[1];
    const int*    li   = (const int*)   d_in[2];
    // d_in[3] = pos_idx (unused)
    const int*    fi   = (const int*)   d_in[4];
    float4*       out  = (float4*)      d_out;

    const int nnz  = in_sizes[1];                // 131072 (divisible by 8)
    const int grid = nnz / ROWS_PER_CTA;         // 16384

    gather_scale_kernel<<<grid, VEC_PER_ROW>>>(W, vals, li, fi, out);
}